// round 15
// baseline (speedup 1.0000x reference)
#include <cuda_runtime.h>

#define NB 64
#define NM 80
#define NT 4000
#define ROWS (NB * NM)        // 5120
#define NCHF 250              // fine chunks per row
#define LCF 16                // fine chunk length
#define CSTRIDE 252           // padded chunk stride (float4-aligned rows)
#define CPH 125               // chunks per half-row
#define GATE_BLOCKS 500       // 500*128 = 64000 gate threads
#define SUM_BLOCKS 10000      // 10000*128 = 1.28M summary threads

__device__ float g_gate[NB * NT];
__device__ float g_Bn[ROWS * CSTRIDE];   // [row][chunk]
__device__ float g_Bs[ROWS * CSTRIDE];
__device__ float g_Sn[ROWS * CSTRIDE];   // [row][chunk]
__device__ float g_Ss[ROWS * CSTRIDE];

__device__ __forceinline__ float clampf(float x, float lo, float hi) {
    return fminf(fmaxf(x, lo), hi);
}
__device__ __forceinline__ float sigmoidf(float x) {
    return 1.0f / (1.0f + __expf(-x));
}

// ---------------------------------------------------------------------------
// Kernel 1 (fused): gate blocks + fine-chunk summary blocks. (measured 22us)
// ---------------------------------------------------------------------------
__global__ void __launch_bounds__(128) k1_gate_sum(
    const float* __restrict__ mel,
    const float* __restrict__ gate_temp,
    const float* __restrict__ ls_ns, const float* __restrict__ ls_st)
{
    if (blockIdx.x < GATE_BLOCKS) {
        // ---------------- gate role ----------------
        int idx = blockIdx.x * 128 + threadIdx.x;   // < 64000 exactly
        int b  = idx / (NT / 4);
        int t4 = idx - b * (NT / 4);

        const float4* base = reinterpret_cast<const float4*>(mel)
                             + (size_t)b * NM * (NT / 4) + t4;

        float sum[4]  = {0.f, 0.f, 0.f, 0.f};
        float low[4]  = {0.f, 0.f, 0.f, 0.f};
        float high[4] = {0.f, 0.f, 0.f, 0.f};
        float lp[4]   = {0.f, 0.f, 0.f, 0.f};

        #pragma unroll
        for (int g = 0; g < 4; ++g) {
            float p[4] = {1.f, 1.f, 1.f, 1.f};
            #pragma unroll
            for (int j = 0; j < 20; ++j) {
                const int m = g * 20 + j;
                float4 v = base[(size_t)m * (NT / 4)];
                float xv[4] = {v.x, v.y, v.z, v.w};
                #pragma unroll
                for (int k = 0; k < 4; ++k) {
                    sum[k] += xv[k];
                    p[k]   *= xv[k] + 1e-8f;
                    if (m < 26)  low[k]  += xv[k];   // M//3 = 26
                    if (m >= 53) high[k] += xv[k];   // 2*M//3 = 53
                }
            }
            #pragma unroll
            for (int k = 0; k < 4; ++k) lp[k] += __log2f(p[k]);
        }

        const float gt = gate_temp[0];
        float4 gout;
        float* go = &gout.x;
        #pragma unroll
        for (int k = 0; k < 4; ++k) {
            float arith = sum[k] * (1.0f / NM) + 1e-8f;
            float geo   = __powf(2.0f, lp[k] * (1.0f / NM));
            float sf    = clampf(__fdividef(geo, arith), 0.f, 1.f);
            float lo_   = low[k]  * (1.0f / 26.0f);
            float hi_   = high[k] * (1.0f / 27.0f);
            float tilt  = clampf(__fdividef(lo_, lo_ + hi_ + 1e-8f), 0.f, 1.f);
            float sfa   = sf + (1.0f - sf) * fmaxf(tilt - 0.6f, 0.f);
            go[k] = sigmoidf(gt * (sfa - 0.5f));
        }
        reinterpret_cast<float4*>(g_gate)[idx] = gout;
    } else {
        // ---------------- summary role ----------------
        int tid = (blockIdx.x - GATE_BLOCKS) * 128 + threadIdx.x;  // < 1.28M
        int row   = tid / NCHF;
        int chunk = tid - row * NCHF;
        int m = row % NM;

        const float s_ns = clampf(sigmoidf(ls_ns[m]), 0.05f, 0.3f);
        const float a_ns = 1.0f - s_ns;
        const float s_st = clampf(sigmoidf(ls_st[m]), 0.05f, 0.3f);
        const float a_st = 1.0f - s_st;

        const float a2n = a_ns * a_ns, a4n = a2n * a2n;
        const float a2s = a_st * a_st, a4s = a2s * a2s;
        const float sa1n = s_ns * a_ns, sa2n = s_ns * a2n, sa3n = sa2n * a_ns;
        const float sa1s = s_st * a_st, sa2s = s_st * a2s, sa3s = sa2s * a_st;

        const float* x = mel + (size_t)row * NT + chunk * LCF;

        float Bn = 0.f, Bs = 0.f;
        #pragma unroll
        for (int i = 0; i < LCF; i += 4) {
            float4 v = *reinterpret_cast<const float4*>(x + i);
            float pn = fmaf(sa3n, v.x, fmaf(sa2n, v.y, fmaf(sa1n, v.z, s_ns * v.w)));
            float ps = fmaf(sa3s, v.x, fmaf(sa2s, v.y, fmaf(sa1s, v.z, s_st * v.w)));
            Bn = fmaf(a4n, Bn, pn);
            Bs = fmaf(a4s, Bs, ps);
        }
        g_Bn[row * CSTRIDE + chunk] = Bn;
        g_Bs[row * CSTRIDE + chunk] = Bs;
    }
}

// ---------------------------------------------------------------------------
// Kernel 2: per-row serial scan over 250 fine-chunk summaries -> exact seeds.
// ---------------------------------------------------------------------------
__global__ void __launch_bounds__(64) k2_scan(
    const float* __restrict__ mel,
    const float* __restrict__ ls_ns, const float* __restrict__ ls_st)
{
    int r = blockIdx.x * 64 + threadIdx.x;
    if (r >= ROWS) return;
    int m = r % NM;

    const float s_ns = clampf(sigmoidf(ls_ns[m]), 0.05f, 0.3f);
    const float a_ns = 1.0f - s_ns;
    const float s_st = clampf(sigmoidf(ls_st[m]), 0.05f, 0.3f);
    const float a_st = 1.0f - s_st;

    // A = a^16
    float a2n = a_ns * a_ns, a4n = a2n * a2n, a8n = a4n * a4n;
    const float An = a8n * a8n;
    float a2s = a_st * a_st, a4s = a2s * a2s, a8s = a4s * a4s;
    const float As = a8s * a8s;

    float Sn = mel[(size_t)r * NT];   // S_{-1} = x_0
    float Ss = Sn;

    const int base = r * CSTRIDE;
    float4 Bn4 = *reinterpret_cast<const float4*>(g_Bn + base);
    float4 Bs4 = *reinterpret_cast<const float4*>(g_Bs + base);
    for (int k = 0; k < 248; k += 4) {
        float4 Bn_c = Bn4, Bs_c = Bs4;
        if (k + 4 < 248) {
            Bn4 = *reinterpret_cast<const float4*>(g_Bn + base + k + 4);
            Bs4 = *reinterpret_cast<const float4*>(g_Bs + base + k + 4);
        }
        float4 Sn4, Ss4;
        Sn4.x = Sn; Sn = fmaf(An, Sn, Bn_c.x);
        Sn4.y = Sn; Sn = fmaf(An, Sn, Bn_c.y);
        Sn4.z = Sn; Sn = fmaf(An, Sn, Bn_c.z);
        Sn4.w = Sn; Sn = fmaf(An, Sn, Bn_c.w);
        Ss4.x = Ss; Ss = fmaf(As, Ss, Bs_c.x);
        Ss4.y = Ss; Ss = fmaf(As, Ss, Bs_c.y);
        Ss4.z = Ss; Ss = fmaf(As, Ss, Bs_c.z);
        Ss4.w = Ss; Ss = fmaf(As, Ss, Bs_c.w);
        *reinterpret_cast<float4*>(g_Sn + base + k) = Sn4;
        *reinterpret_cast<float4*>(g_Ss + base + k) = Ss4;
    }
    #pragma unroll
    for (int k = 248; k < NCHF; ++k) {
        g_Sn[base + k] = Sn;
        g_Ss[base + k] = Ss;
        Sn = fmaf(An, Sn, g_Bn[base + k]);
        Ss = fmaf(As, Ss, g_Bs[base + k]);
    }
}

// ---------------------------------------------------------------------------
// Kernel 3: main PCEN, double-buffered cp.async pipeline.
// Block = full row; halves of 2000 elems staged via cp.async (no regs).
// Compute half0 overlaps the in-flight loads of half1; STG of half0 drains
// during compute of half1. (128,5): 102-reg cap, 40KB smem, 5 blocks/SM.
// ---------------------------------------------------------------------------
__global__ void __launch_bounds__(128, 5) k3_pcen(
    const float* __restrict__ mel,
    const float* __restrict__ ls_ns, const float* __restrict__ la_ns,
    const float* __restrict__ ld_ns, const float* __restrict__ lr_ns,
    const float* __restrict__ ls_st, const float* __restrict__ la_st,
    const float* __restrict__ ld_st, const float* __restrict__ lr_st,
    float* __restrict__ out)
{
    __shared__ float sx[2][CPH * 20];   // 2 x 10 KB: x in, out in-place
    __shared__ float sg[2][CPH * 20];   // 2 x 10 KB: gate

    const int tid = threadIdx.x;
    const int row = blockIdx.x;
    const int b = row / NM;
    const int m = row - b * NM;

    const float4* xg = reinterpret_cast<const float4*>(mel + (size_t)row * NT);
    const float4* gg = reinterpret_cast<const float4*>(g_gate + (size_t)b * NT);
    float4* og = reinterpret_cast<float4*>(out + (size_t)row * NT);

    // ---- issue async stage-in for both halves ----
    #pragma unroll
    for (int h = 0; h < 2; ++h) {
        #pragma unroll
        for (int it = 0; it < 4; ++it) {
            int f = it * 128 + tid;
            if (f < 500) {
                int d = (f >> 2) * 5 + (f & 3);
                unsigned ax = (unsigned)__cvta_generic_to_shared(
                    reinterpret_cast<float4*>(sx[h]) + d);
                unsigned ag = (unsigned)__cvta_generic_to_shared(
                    reinterpret_cast<float4*>(sg[h]) + d);
                asm volatile("cp.async.cg.shared.global [%0], [%1], 16;\n"
                             :: "r"(ax), "l"(xg + h * 500 + f));
                asm volatile("cp.async.cg.shared.global [%0], [%1], 16;\n"
                             :: "r"(ag), "l"(gg + h * 500 + f));
            }
        }
        asm volatile("cp.async.commit_group;\n");
    }

    // ---- per-channel params (overlap with loads) ----
    const float s_ns  = clampf(sigmoidf(ls_ns[m]), 0.05f, 0.3f);
    const float a_ns  = 1.0f - s_ns;
    const float a2n = a_ns * a_ns, a3n = a2n * a_ns, a4n = a2n * a2n;
    const float al_ns = clampf(sigmoidf(la_ns[m]), 0.9f, 0.999f);
    const float d_ns  = clampf(__expf(ld_ns[m]), 0.5f, 5.0f);
    const float r_ns  = clampf(sigmoidf(lr_ns[m]), 0.05f, 0.25f);
    const float dp_ns = __powf(d_ns, r_ns);

    const float s_st  = clampf(sigmoidf(ls_st[m]), 0.05f, 0.3f);
    const float a_st  = 1.0f - s_st;
    const float a2s = a_st * a_st, a3s = a2s * a_st, a4s = a2s * a2s;
    const float al_st = clampf(sigmoidf(la_st[m]), 0.9f, 0.999f);
    const float d_st  = clampf(__expf(ld_st[m]), 0.001f, 0.1f);
    const float r_st  = clampf(sigmoidf(lr_st[m]), 0.05f, 0.25f);
    const float dp_st = __powf(d_st, r_st);

#define PCEN_OUT(smn, sms, xx, gg_, oo) do {                           \
        float gn = __powf(1e-6f + (smn), -al_ns);                      \
        float on = __powf(fmaf((xx), gn, d_ns), r_ns) - dp_ns;         \
        float gs = __powf(1e-6f + (sms), -al_st);                      \
        float os = __powf(fmaf((xx), gs, d_st), r_st) - dp_st;         \
        (oo) = fmaf((gg_), os - on, on);                               \
    } while (0)

#define COMPUTE_HALF(h)                                                 \
    if (tid < CPH) {                                                    \
        float smn = g_Sn[row * CSTRIDE + (h) * CPH + tid];              \
        float sms = g_Ss[row * CSTRIDE + (h) * CPH + tid];              \
        _Pragma("unroll 1")                                             \
        for (int k = 0; k < 4; ++k) {                                   \
            float4 v = reinterpret_cast<float4*>(sx[h])[tid * 5 + k];   \
            float4 g = reinterpret_cast<float4*>(sg[h])[tid * 5 + k];   \
            float u1n = fmaf(a_ns, v.x, v.y);                           \
            float u2n = fmaf(a_ns, u1n, v.z);                           \
            float u3n = fmaf(a_ns, u2n, v.w);                           \
            float u1s = fmaf(a_st, v.x, v.y);                           \
            float u2s = fmaf(a_st, u1s, v.z);                           \
            float u3s = fmaf(a_st, u2s, v.w);                           \
            float n1 = fmaf(a_ns, smn, s_ns * v.x);                     \
            float n2 = fmaf(a2n,  smn, s_ns * u1n);                     \
            float n3 = fmaf(a3n,  smn, s_ns * u2n);                     \
            float n4 = fmaf(a4n,  smn, s_ns * u3n);                     \
            float t1 = fmaf(a_st, sms, s_st * v.x);                     \
            float t2 = fmaf(a2s,  sms, s_st * u1s);                     \
            float t3 = fmaf(a3s,  sms, s_st * u2s);                     \
            float t4 = fmaf(a4s,  sms, s_st * u3s);                     \
            smn = n4;                                                   \
            sms = t4;                                                   \
            float4 ov;                                                  \
            PCEN_OUT(n1, t1, v.x, g.x, ov.x);                           \
            PCEN_OUT(n2, t2, v.y, g.y, ov.y);                           \
            PCEN_OUT(n3, t3, v.z, g.z, ov.z);                           \
            PCEN_OUT(n4, t4, v.w, g.w, ov.w);                           \
            reinterpret_cast<float4*>(sx[h])[tid * 5 + k] = ov;         \
        }                                                               \
    }

#define STORE_HALF(h)                                                   \
    _Pragma("unroll")                                                   \
    for (int it = 0; it < 4; ++it) {                                    \
        int f = it * 128 + tid;                                         \
        if (f < 500) {                                                  \
            int d = (f >> 2) * 5 + (f & 3);                             \
            og[(h) * 500 + f] = reinterpret_cast<float4*>(sx[h])[d];    \
        }                                                               \
    }

    // half 0 ready?
    asm volatile("cp.async.wait_group 1;\n");
    __syncthreads();
    COMPUTE_HALF(0)
    __syncthreads();
    STORE_HALF(0)            // STGs drain during compute of half 1

    // half 1 ready?
    asm volatile("cp.async.wait_group 0;\n");
    __syncthreads();
    COMPUTE_HALF(1)
    __syncthreads();
    STORE_HALF(1)

#undef STORE_HALF
#undef COMPUTE_HALF
#undef PCEN_OUT
}

extern "C" void kernel_launch(void* const* d_in, const int* in_sizes, int n_in,
                              void* d_out, int out_size)
{
    const float* mel = (const float*)d_in[0];
    const float* ls_ns = (const float*)d_in[1];
    const float* la_ns = (const float*)d_in[2];
    const float* ld_ns = (const float*)d_in[3];
    const float* lr_ns = (const float*)d_in[4];
    const float* ls_st = (const float*)d_in[5];
    const float* la_st = (const float*)d_in[6];
    const float* ld_st = (const float*)d_in[7];
    const float* lr_st = (const float*)d_in[8];
    const float* gate_temp = (const float*)d_in[9];
    float* out = (float*)d_out;

    k1_gate_sum<<<GATE_BLOCKS + SUM_BLOCKS, 128>>>(mel, gate_temp, ls_ns, ls_st);
    k2_scan<<<(ROWS + 63) / 64, 64>>>(mel, ls_ns, ls_st);
    k3_pcen<<<ROWS, 128>>>(
        mel, ls_ns, la_ns, ld_ns, lr_ns, ls_st, la_st, ld_st, lr_st, out);
}

// round 16
// speedup vs baseline: 1.8372x; 1.8372x over previous
#include <cuda_runtime.h>

#define NB 64
#define NM 80
#define NT 4000
#define ROWS (NB * NM)        // 5120
#define NCHF 250              // fine chunks per row
#define LCF 16                // fine chunk length
#define CSTRIDE 252           // padded chunk stride (float4-aligned rows)
#define CPH 125               // chunks per half-row
#define GATE_BLOCKS 500       // 500*128 = 64000 gate threads
#define SUM_BLOCKS 10000      // 10000*128 = 1.28M summary threads

__device__ float g_gate[NB * NT];
__device__ float g_Bn[ROWS * CSTRIDE];   // [row][chunk]
__device__ float g_Bs[ROWS * CSTRIDE];
__device__ float g_Sn[ROWS * CSTRIDE];   // [row][chunk]
__device__ float g_Ss[ROWS * CSTRIDE];

__device__ __forceinline__ float clampf(float x, float lo, float hi) {
    return fminf(fmaxf(x, lo), hi);
}
__device__ __forceinline__ float sigmoidf(float x) {
    return 1.0f / (1.0f + __expf(-x));
}

// ---------------------------------------------------------------------------
// Kernel 1 (fused): gate blocks + fine-chunk summary blocks. (~22us best-case)
// ---------------------------------------------------------------------------
__global__ void __launch_bounds__(128) k1_gate_sum(
    const float* __restrict__ mel,
    const float* __restrict__ gate_temp,
    const float* __restrict__ ls_ns, const float* __restrict__ ls_st)
{
    if (blockIdx.x < GATE_BLOCKS) {
        // ---------------- gate role ----------------
        int idx = blockIdx.x * 128 + threadIdx.x;   // < 64000 exactly
        int b  = idx / (NT / 4);
        int t4 = idx - b * (NT / 4);

        const float4* base = reinterpret_cast<const float4*>(mel)
                             + (size_t)b * NM * (NT / 4) + t4;

        float sum[4]  = {0.f, 0.f, 0.f, 0.f};
        float low[4]  = {0.f, 0.f, 0.f, 0.f};
        float high[4] = {0.f, 0.f, 0.f, 0.f};
        float lp[4]   = {0.f, 0.f, 0.f, 0.f};

        #pragma unroll
        for (int g = 0; g < 4; ++g) {
            float p[4] = {1.f, 1.f, 1.f, 1.f};
            #pragma unroll
            for (int j = 0; j < 20; ++j) {
                const int m = g * 20 + j;
                float4 v = base[(size_t)m * (NT / 4)];
                float xv[4] = {v.x, v.y, v.z, v.w};
                #pragma unroll
                for (int k = 0; k < 4; ++k) {
                    sum[k] += xv[k];
                    p[k]   *= xv[k] + 1e-8f;
                    if (m < 26)  low[k]  += xv[k];   // M//3 = 26
                    if (m >= 53) high[k] += xv[k];   // 2*M//3 = 53
                }
            }
            #pragma unroll
            for (int k = 0; k < 4; ++k) lp[k] += __log2f(p[k]);
        }

        const float gt = gate_temp[0];
        float4 gout;
        float* go = &gout.x;
        #pragma unroll
        for (int k = 0; k < 4; ++k) {
            float arith = sum[k] * (1.0f / NM) + 1e-8f;
            float geo   = __powf(2.0f, lp[k] * (1.0f / NM));
            float sf    = clampf(__fdividef(geo, arith), 0.f, 1.f);
            float lo_   = low[k]  * (1.0f / 26.0f);
            float hi_   = high[k] * (1.0f / 27.0f);
            float tilt  = clampf(__fdividef(lo_, lo_ + hi_ + 1e-8f), 0.f, 1.f);
            float sfa   = sf + (1.0f - sf) * fmaxf(tilt - 0.6f, 0.f);
            go[k] = sigmoidf(gt * (sfa - 0.5f));
        }
        reinterpret_cast<float4*>(g_gate)[idx] = gout;
    } else {
        // ---------------- summary role ----------------
        int tid = (blockIdx.x - GATE_BLOCKS) * 128 + threadIdx.x;  // < 1.28M
        int row   = tid / NCHF;
        int chunk = tid - row * NCHF;
        int m = row % NM;

        const float s_ns = clampf(sigmoidf(ls_ns[m]), 0.05f, 0.3f);
        const float a_ns = 1.0f - s_ns;
        const float s_st = clampf(sigmoidf(ls_st[m]), 0.05f, 0.3f);
        const float a_st = 1.0f - s_st;

        const float a2n = a_ns * a_ns, a4n = a2n * a2n;
        const float a2s = a_st * a_st, a4s = a2s * a2s;
        const float sa1n = s_ns * a_ns, sa2n = s_ns * a2n, sa3n = sa2n * a_ns;
        const float sa1s = s_st * a_st, sa2s = s_st * a2s, sa3s = sa2s * a_st;

        const float* x = mel + (size_t)row * NT + chunk * LCF;

        float Bn = 0.f, Bs = 0.f;
        #pragma unroll
        for (int i = 0; i < LCF; i += 4) {
            float4 v = *reinterpret_cast<const float4*>(x + i);
            float pn = fmaf(sa3n, v.x, fmaf(sa2n, v.y, fmaf(sa1n, v.z, s_ns * v.w)));
            float ps = fmaf(sa3s, v.x, fmaf(sa2s, v.y, fmaf(sa1s, v.z, s_st * v.w)));
            Bn = fmaf(a4n, Bn, pn);
            Bs = fmaf(a4s, Bs, ps);
        }
        g_Bn[row * CSTRIDE + chunk] = Bn;
        g_Bs[row * CSTRIDE + chunk] = Bs;
    }
}

// ---------------------------------------------------------------------------
// Kernel 2: warp-per-row affine scan over 250 chunk summaries -> exact seeds.
// 8 segments of 32 chunks; lane = chunk (coalesced ld/st); Kogge-Stone
// compose within segment; serial carry across 8 segments. A^k underflow for
// distant chunks is benign (true weight below float range ⇒ contribution ~0).
// ---------------------------------------------------------------------------
__global__ void __launch_bounds__(256) k2_scan(
    const float* __restrict__ mel,
    const float* __restrict__ ls_ns, const float* __restrict__ ls_st)
{
    const int row  = blockIdx.x * 8 + (threadIdx.x >> 5);   // 640 blocks
    const int lane = threadIdx.x & 31;
    const int m = row % NM;

    const float s_ns = clampf(sigmoidf(ls_ns[m]), 0.05f, 0.3f);
    const float a_ns = 1.0f - s_ns;
    const float s_st = clampf(sigmoidf(ls_st[m]), 0.05f, 0.3f);
    const float a_st = 1.0f - s_st;

    // A = a^16
    float a2n = a_ns * a_ns, a4n = a2n * a2n, a8n = a4n * a4n;
    const float A16n = a8n * a8n;
    float a2s = a_st * a_st, a4s = a2s * a2s, a8s = a4s * a4s;
    const float A16s = a8s * a8s;

    float Sn = mel[(size_t)row * NT];   // S_{-1} = x_0
    float Ss = Sn;

    const int base = row * CSTRIDE;
    #pragma unroll 1
    for (int seg = 0; seg < 8; ++seg) {
        int c = seg * 32 + lane;
        bool ok = (c < NCHF);
        float Bn = ok ? g_Bn[base + c] : 0.f;
        float Bs = ok ? g_Bs[base + c] : 0.f;
        float An = A16n, As = A16s;

        // inclusive Kogge-Stone scan of affine pairs (prefix-first compose)
        #pragma unroll
        for (int d = 1; d < 32; d <<= 1) {
            float Ap = __shfl_up_sync(0xffffffffu, An, d);
            float Bp = __shfl_up_sync(0xffffffffu, Bn, d);
            float Aq = __shfl_up_sync(0xffffffffu, As, d);
            float Bq = __shfl_up_sync(0xffffffffu, Bs, d);
            if (lane >= d) {
                Bn = fmaf(An, Bp, Bn); An *= Ap;
                Bs = fmaf(As, Bq, Bs); As *= Aq;
            }
        }

        // exclusive prefix -> seed entering chunk c
        float AnE = __shfl_up_sync(0xffffffffu, An, 1);
        float BnE = __shfl_up_sync(0xffffffffu, Bn, 1);
        float AsE = __shfl_up_sync(0xffffffffu, As, 1);
        float BsE = __shfl_up_sync(0xffffffffu, Bs, 1);
        if (lane == 0) { AnE = 1.f; BnE = 0.f; AsE = 1.f; BsE = 0.f; }
        if (ok) {
            g_Sn[base + c] = fmaf(AnE, Sn, BnE);
            g_Ss[base + c] = fmaf(AsE, Ss, BsE);
        }

        // segment carry from lane 31 inclusive
        float An31 = __shfl_sync(0xffffffffu, An, 31);
        float Bn31 = __shfl_sync(0xffffffffu, Bn, 31);
        float As31 = __shfl_sync(0xffffffffu, As, 31);
        float Bs31 = __shfl_sync(0xffffffffu, Bs, 31);
        Sn = fmaf(An31, Sn, Bn31);
        Ss = fmaf(As31, Ss, Bs31);
    }
}

// ---------------------------------------------------------------------------
// Kernel 3: main PCEN. Block = HALF row (2000 elems = 125 chunks of 16).
// Coalesced SMEM staging (20 KB/block); thread = one chunk; seeds coalesced.
// (128,7): 73-reg cap, 7 blocks x 4 warps = 28 warps/SM -> phase stagger
// hides staging DRAM latency behind other blocks' MUFU work.
// ---------------------------------------------------------------------------
__global__ void __launch_bounds__(128, 7) k3_pcen(
    const float* __restrict__ mel,
    const float* __restrict__ ls_ns, const float* __restrict__ la_ns,
    const float* __restrict__ ld_ns, const float* __restrict__ lr_ns,
    const float* __restrict__ ls_st, const float* __restrict__ la_st,
    const float* __restrict__ ld_st, const float* __restrict__ lr_st,
    float* __restrict__ out)
{
    __shared__ float sx[CPH * 20];   // 10 KB: x in, out in-place (padded)
    __shared__ float sg[CPH * 20];   // 10 KB: gate (padded)

    const int tid  = threadIdx.x;
    const int row  = blockIdx.x >> 1;
    const int half = blockIdx.x & 1;
    const int b = row / NM;
    const int m = row - b * NM;

    const float4* xg = reinterpret_cast<const float4*>(mel + (size_t)row * NT + half * 2000);
    const float4* gg = reinterpret_cast<const float4*>(g_gate + (size_t)b * NT + half * 2000);
    float4* og = reinterpret_cast<float4*>(out + (size_t)row * NT + half * 2000);

    // ---- stage in (coalesced): 500 float4s, padded 5-slot chunks ----
    #pragma unroll
    for (int it = 0; it < 4; ++it) {
        int f = it * 128 + tid;
        if (f < 500) {
            int d = (f >> 2) * 5 + (f & 3);
            reinterpret_cast<float4*>(sx)[d] = xg[f];
            reinterpret_cast<float4*>(sg)[d] = gg[f];
        }
    }

    // ---- per-channel params ----
    const float s_ns  = clampf(sigmoidf(ls_ns[m]), 0.05f, 0.3f);
    const float a_ns  = 1.0f - s_ns;
    const float a2n = a_ns * a_ns, a3n = a2n * a_ns, a4n = a2n * a2n;
    const float al_ns = clampf(sigmoidf(la_ns[m]), 0.9f, 0.999f);
    const float d_ns  = clampf(__expf(ld_ns[m]), 0.5f, 5.0f);
    const float r_ns  = clampf(sigmoidf(lr_ns[m]), 0.05f, 0.25f);
    const float dp_ns = __powf(d_ns, r_ns);

    const float s_st  = clampf(sigmoidf(ls_st[m]), 0.05f, 0.3f);
    const float a_st  = 1.0f - s_st;
    const float a2s = a_st * a_st, a3s = a2s * a_st, a4s = a2s * a2s;
    const float al_st = clampf(sigmoidf(la_st[m]), 0.9f, 0.999f);
    const float d_st  = clampf(__expf(ld_st[m]), 0.001f, 0.1f);
    const float r_st  = clampf(sigmoidf(lr_st[m]), 0.05f, 0.25f);
    const float dp_st = __powf(d_st, r_st);

    __syncthreads();

#define PCEN_OUT(smn, sms, xx, gg_, oo) do {                           \
        float gn = __powf(1e-6f + (smn), -al_ns);                      \
        float on = __powf(fmaf((xx), gn, d_ns), r_ns) - dp_ns;         \
        float gs = __powf(1e-6f + (sms), -al_st);                      \
        float os = __powf(fmaf((xx), gs, d_st), r_st) - dp_st;         \
        (oo) = fmaf((gg_), os - on, on);                               \
    } while (0)

    if (tid < CPH) {
        float smn = g_Sn[row * CSTRIDE + half * CPH + tid];   // coalesced
        float sms = g_Ss[row * CSTRIDE + half * CPH + tid];

        #pragma unroll 1
        for (int k = 0; k < 4; ++k) {
            float4 v = reinterpret_cast<float4*>(sx)[tid * 5 + k];
            float4 g = reinterpret_cast<float4*>(sg)[tid * 5 + k];

            float u1n = fmaf(a_ns, v.x, v.y);
            float u2n = fmaf(a_ns, u1n, v.z);
            float u3n = fmaf(a_ns, u2n, v.w);
            float u1s = fmaf(a_st, v.x, v.y);
            float u2s = fmaf(a_st, u1s, v.z);
            float u3s = fmaf(a_st, u2s, v.w);

            float n1 = fmaf(a_ns, smn, s_ns * v.x);
            float n2 = fmaf(a2n,  smn, s_ns * u1n);
            float n3 = fmaf(a3n,  smn, s_ns * u2n);
            float n4 = fmaf(a4n,  smn, s_ns * u3n);
            float t1 = fmaf(a_st, sms, s_st * v.x);
            float t2 = fmaf(a2s,  sms, s_st * u1s);
            float t3 = fmaf(a3s,  sms, s_st * u2s);
            float t4 = fmaf(a4s,  sms, s_st * u3s);
            smn = n4;
            sms = t4;

            float4 ov;
            PCEN_OUT(n1, t1, v.x, g.x, ov.x);
            PCEN_OUT(n2, t2, v.y, g.y, ov.y);
            PCEN_OUT(n3, t3, v.z, g.z, ov.z);
            PCEN_OUT(n4, t4, v.w, g.w, ov.w);
            reinterpret_cast<float4*>(sx)[tid * 5 + k] = ov;   // in-place
        }
    }
#undef PCEN_OUT

    __syncthreads();

    // ---- stage out (coalesced) ----
    #pragma unroll
    for (int it = 0; it < 4; ++it) {
        int f = it * 128 + tid;
        if (f < 500) {
            int d = (f >> 2) * 5 + (f & 3);
            og[f] = reinterpret_cast<float4*>(sx)[d];
        }
    }
}

extern "C" void kernel_launch(void* const* d_in, const int* in_sizes, int n_in,
                              void* d_out, int out_size)
{
    const float* mel = (const float*)d_in[0];
    const float* ls_ns = (const float*)d_in[1];
    const float* la_ns = (const float*)d_in[2];
    const float* ld_ns = (const float*)d_in[3];
    const float* lr_ns = (const float*)d_in[4];
    const float* ls_st = (const float*)d_in[5];
    const float* la_st = (const float*)d_in[6];
    const float* ld_st = (const float*)d_in[7];
    const float* lr_st = (const float*)d_in[8];
    const float* gate_temp = (const float*)d_in[9];
    float* out = (float*)d_out;

    k1_gate_sum<<<GATE_BLOCKS + SUM_BLOCKS, 128>>>(mel, gate_temp, ls_ns, ls_st);
    k2_scan<<<ROWS / 8, 256>>>(mel, ls_ns, ls_st);
    k3_pcen<<<ROWS * 2, 128>>>(
        mel, ls_ns, la_ns, ld_ns, lr_ns, ls_st, la_st, ld_st, lr_st, out);
}